// round 15
// baseline (speedup 1.0000x reference)
#include <cuda_runtime.h>
#include <cuda_fp16.h>
#include <cstdint>

// GridEncoder (instant-ngp style), D=3, L=16, C=2, H=16, PLS=2, log2_hashmap=19,
// align_corners=false.
//
// R14 = R13 (roofline main kernel: quad-fused hash pairs + dense cell records,
// 2 levels/thread, float4 evict-first stores) + complement-pair table for the
// hash far path (retry of R10 now that __stcs keeps tables L2-resident):
//   far pair: one LDG.64 from pairR gives eA always and eB when diff==7;
//   only diff>7 (12.5% of pairs) needs the second LDG.32.
//   Hash lines/pl: 5 -> 4.5.

#define PRIME1 2654435761u
#define PRIME2 805459861u
#define HASH_MASK 0x7FFFFu
#define TOTAL_PARAMS 7131240
#define NCELLS 299008            // 16^3 + 32^3 + 64^3
#define HSTART 315496            // c_off[3]: start of hash region
#define HCOUNT 6815744           // 13 * 2^19 hash entries
#define HOCTS (HCOUNT / 8)       // 851,968 8-entry blocks
#define NPAIRR (HCOUNT / 2)      // uint2 records in pairR

__device__ __align__(16) __half2 g_embh[TOTAL_PARAMS];   // half2 table (hash region used)
__device__ __align__(32) uint4   g_celld[2 * NCELLS];    // 9.6 MB dense cell table
__device__ __align__(16) uint2   g_pairR[NPAIRR];        // 27.3 MB complement pairs

__constant__ uint32_t c_off[16] = {
    0u, 4920u, 40864u, 315496u,
    839784u, 1364072u, 1888360u, 2412648u,
    2936936u, 3461224u, 3985512u, 4509800u,
    5034088u, 5558376u, 6082664u, 6606952u
};
__constant__ float c_scale[16] = {
    15.f, 31.f, 63.f, 127.f, 255.f, 511.f, 1023.f, 2047.f,
    4095.f, 8191.f, 16383.f, 32767.f, 65535.f, 131071.f, 262143.f, 524287.f
};
__constant__ uint32_t c_celloff[3] = {0u, 4096u, 36864u};

__device__ __forceinline__ uint32_t f2h2(float a, float b)
{
    __half2 h = __floats2half2_rn(a, b);
    return *reinterpret_cast<uint32_t*>(&h);
}

// Fused prep:
//  blocks [0, ho_blocks): per thread, one 8-entry hash block -> half2 quads
//    AND the 4 complement-pair records (same fp32 reads, 4 STG.128 total).
//  remaining blocks: dense cell records from the fp32 source.
__global__ void __launch_bounds__(256)
prep_kernel(const float4* __restrict__ emb4, const float2* __restrict__ emb2,
            int ho_blocks)
{
    if (blockIdx.x < (unsigned)ho_blocks) {
        int i = blockIdx.x * 256 + threadIdx.x;
        if (i < HOCTS) {
            int src = (HSTART / 2) + 4 * i;   // float4 index into fp32 table
            float4 v0 = __ldg(&emb4[src + 0]);
            float4 v1 = __ldg(&emb4[src + 1]);
            float4 v2 = __ldg(&emb4[src + 2]);
            float4 v3 = __ldg(&emb4[src + 3]);

            uint32_t h0 = f2h2(v0.x, v0.y), h1 = f2h2(v0.z, v0.w);
            uint32_t h2 = f2h2(v1.x, v1.y), h3 = f2h2(v1.z, v1.w);
            uint32_t h4 = f2h2(v2.x, v2.y), h5 = f2h2(v2.z, v2.w);
            uint32_t h6 = f2h2(v3.x, v3.y), h7 = f2h2(v3.z, v3.w);

            uint4* dst = reinterpret_cast<uint4*>(g_embh + HSTART) + 2 * i;
            dst[0] = make_uint4(h0, h1, h2, h3);
            dst[1] = make_uint4(h4, h5, h6, h7);

            // complement-pair records q=0..3: (E[b+q], E[b+7-q])
            uint4* pr = reinterpret_cast<uint4*>(g_pairR + 4 * (size_t)i);
            pr[0] = make_uint4(h0, h7, h1, h6);
            pr[1] = make_uint4(h2, h5, h3, h4);
        }
    } else {
        int i = (blockIdx.x - ho_blocks) * 256 + threadIdx.x;
        if (i >= NCELLS) return;

        uint32_t lc, sft, base, off;
        if (i < 4096)        { lc = i;          sft = 4u; base = 17u; off = 0u; }
        else if (i < 36864)  { lc = i - 4096;   sft = 5u; base = 33u; off = 4920u; }
        else                 { lc = i - 36864;  sft = 6u; base = 65u; off = 40864u; }

        uint32_t mask = (1u << sft) - 1u;
        uint32_t gx = lc & mask;
        uint32_t gy = (lc >> sft) & mask;
        uint32_t gz = lc >> (2u * sft);

        uint32_t b2 = base * base;
        uint32_t s = off + gx + gy * base + gz * b2;

        float2 v00a = __ldg(&emb2[s]);
        float2 v00b = __ldg(&emb2[s + 1u]);
        float2 v10a = __ldg(&emb2[s + base]);
        float2 v10b = __ldg(&emb2[s + base + 1u]);
        float2 v01a = __ldg(&emb2[s + b2]);
        float2 v01b = __ldg(&emb2[s + b2 + 1u]);
        float2 v11a = __ldg(&emb2[s + base + b2]);
        float2 v11b = __ldg(&emb2[s + base + b2 + 1u]);

        uint4 qa, qb;
        qa.x = f2h2(v00a.x, v00a.y);  qa.y = f2h2(v00b.x, v00b.y);
        qa.z = f2h2(v10a.x, v10a.y);  qa.w = f2h2(v10b.x, v10b.y);
        qb.x = f2h2(v01a.x, v01a.y);  qb.y = f2h2(v01b.x, v01b.y);
        qb.z = f2h2(v11a.x, v11a.y);  qb.w = f2h2(v11b.x, v11b.y);

        g_celld[2 * i + 0] = qa;
        g_celld[2 * i + 1] = qb;
    }
}

__device__ __forceinline__ uint32_t pick4(uint4 q, uint32_t k)
{
    uint32_t lo = (k & 1u) ? q.y : q.x;
    uint32_t hi = (k & 1u) ? q.w : q.z;
    return (k & 2u) ? hi : lo;
}

__device__ __forceinline__ float2 h2f(uint32_t h)
{
    __half2 v = *reinterpret_cast<__half2*>(&h);
    return __half22float2(v);
}

// Hash-level pair load: near = one 16B quad (75%); far = one LDG.64 from the
// complement-pair table (+ one LDG.32 only when diff > 7).
__device__ __forceinline__ void load_pair(uint32_t iA, uint32_t iB,
                                          float2& ea, float2& eb)
{
    uint32_t diff = iA ^ iB;
    if (diff < 4u) {
        uint4 q = __ldg(reinterpret_cast<const uint4*>(g_embh + (iA & ~3u)));
        ea = h2f(pick4(q, iA & 3u));
        eb = h2f(pick4(q, iB & 3u));
    } else {
        uint32_t rA = iA - HSTART;
        uint32_t j  = rA & 7u;
        uint32_t q  = (j < 4u) ? j : (7u - j);
        uint2 v = __ldg(&g_pairR[(size_t)(rA >> 3u) * 4u + q]);
        uint32_t ha = (j < 4u) ? v.x : v.y;
        uint32_t hb = (j < 4u) ? v.y : v.x;
        if (diff != 7u)
            hb = __ldg(reinterpret_cast<const uint32_t*>(g_embh) + iB);
        ea = h2f(ha);
        eb = h2f(hb);
    }
}

// One point-level: gathers + trilinear interp. Returns (ch0, ch1).
__device__ __forceinline__ float2 encode_level(int l, float x, float y, float z)
{
    float scale = c_scale[l];
    float px = fmaf(x, scale, 0.5f);
    float py = fmaf(y, scale, 0.5f);
    float pz = fmaf(z, scale, 0.5f);

    float fx = floorf(px), fy = floorf(py), fz = floorf(pz);
    uint32_t gx = (uint32_t)fx, gy = (uint32_t)fy, gz = (uint32_t)fz;
    float rx = px - fx, ry = py - fy, rz = pz - fz;

    float2 e0, e1, e2c, e3, e4c, e5, e6, e7;

    if (l >= 3) {
        uint32_t off = c_off[l];
        uint32_t x0 = gx,              x1 = gx + 1u;
        uint32_t y0 = gy * PRIME1,     y1 = (gy + 1u) * PRIME1;
        uint32_t z0 = gz * PRIME2,     z1 = (gz + 1u) * PRIME2;
        uint32_t h00 = y0 ^ z0, h10 = y1 ^ z0, h01 = y0 ^ z1, h11 = y1 ^ z1;
        uint32_t i00a = ((x0 ^ h00) & HASH_MASK) + off;
        uint32_t i00b = ((x1 ^ h00) & HASH_MASK) + off;
        uint32_t i10a = ((x0 ^ h10) & HASH_MASK) + off;
        uint32_t i10b = ((x1 ^ h10) & HASH_MASK) + off;
        uint32_t i01a = ((x0 ^ h01) & HASH_MASK) + off;
        uint32_t i01b = ((x1 ^ h01) & HASH_MASK) + off;
        uint32_t i11a = ((x0 ^ h11) & HASH_MASK) + off;
        uint32_t i11b = ((x1 ^ h11) & HASH_MASK) + off;

        load_pair(i00a, i00b, e0,  e1);
        load_pair(i10a, i10b, e2c, e3);
        load_pair(i01a, i01b, e4c, e5);
        load_pair(i11a, i11b, e6,  e7);
    } else {
        uint32_t sft = 4u + (uint32_t)l;
        uint32_t cell = c_celloff[l] + gx + (gy << sft) + (gz << (sft + sft));
        const uint4* cp = &g_celld[2u * cell];
        uint4 qa = __ldg(cp);
        uint4 qb = __ldg(cp + 1);
        e0  = h2f(qa.x);  e1 = h2f(qa.y);
        e2c = h2f(qa.z);  e3 = h2f(qa.w);
        e4c = h2f(qb.x);  e5 = h2f(qb.y);
        e6  = h2f(qb.z);  e7 = h2f(qb.w);
    }

    float wx0 = 1.0f - rx, wx1 = rx;
    float wy0 = 1.0f - ry, wy1 = ry;
    float wz0 = 1.0f - rz, wz1 = rz;

    float w00 = wy0 * wz0, w10 = wy1 * wz0, w01 = wy0 * wz1, w11 = wy1 * wz1;

    float w0 = wx0 * w00, w1 = wx1 * w00;
    float w2 = wx0 * w10, w3 = wx1 * w10;
    float w4 = wx0 * w01, w5 = wx1 * w01;
    float w6 = wx0 * w11, w7 = wx1 * w11;

    float a0 = w0 * e0.x;            float a1 = w0 * e0.y;
    a0 = fmaf(w1, e1.x,  a0);        a1 = fmaf(w1, e1.y,  a1);
    a0 = fmaf(w2, e2c.x, a0);        a1 = fmaf(w2, e2c.y, a1);
    a0 = fmaf(w3, e3.x,  a0);        a1 = fmaf(w3, e3.y,  a1);
    a0 = fmaf(w4, e4c.x, a0);        a1 = fmaf(w4, e4c.y, a1);
    a0 = fmaf(w5, e5.x,  a0);        a1 = fmaf(w5, e5.y,  a1);
    a0 = fmaf(w6, e6.x,  a0);        a1 = fmaf(w6, e6.y,  a1);
    a0 = fmaf(w7, e7.x,  a0);        a1 = fmaf(w7, e7.y,  a1);

    return make_float2(a0, a1);
}

__global__ void __launch_bounds__(256)
grid_encode_kernel(const float* __restrict__ in,
                   float4* __restrict__ out,
                   int B)
{
    int t = blockIdx.x * blockDim.x + threadIdx.x;
    int p = t >> 3;           // point index
    int j = t & 7;            // level pair (2j, 2j+1)
    if (p >= B) return;

    float x = (in[p * 3 + 0] + 1.0f) * 0.5f;
    float y = (in[p * 3 + 1] + 1.0f) * 0.5f;
    float z = (in[p * 3 + 2] + 1.0f) * 0.5f;

    float2 r0 = encode_level(2 * j + 0, x, y, z);
    float2 r1 = encode_level(2 * j + 1, x, y, z);

    // evict-first: keep the 63MB table set resident in L2
    __stcs(&out[p * 8 + j], make_float4(r0.x, r0.y, r1.x, r1.y));
}

extern "C" void kernel_launch(void* const* d_in, const int* in_sizes, int n_in,
                              void* d_out, int out_size) {
    const float*  inputs = (const float*)d_in[0];       // [B, 3]
    const float4* emb4   = (const float4*)d_in[1];      // fp32 table as float4
    const float2* emb2   = (const float2*)d_in[1];      // fp32 table as float2
    float4*       out    = (float4*)d_out;              // [B, 8] of float4

    int B = in_sizes[0] / 3;

    // 1) fused prep: hash convert + pairR build + dense cell build
    int ho_blocks   = (HOCTS + 255) / 256;
    int cell_blocks = (NCELLS + 255) / 256;
    prep_kernel<<<ho_blocks + cell_blocks, 256>>>(emb4, emb2, ho_blocks);

    // 2) main encode: 8 threads per point, 2 levels each
    int threads = 256;
    long long total = (long long)B * 8;
    int blocks = (int)((total + threads - 1) / threads);
    grid_encode_kernel<<<blocks, threads>>>(inputs, out, B);
}

// round 16
// speedup vs baseline: 1.0561x; 1.0561x over previous
#include <cuda_runtime.h>
#include <cuda_fp16.h>
#include <cstdint>

// GridEncoder (instant-ngp style), D=3, L=16, C=2, H=16, PLS=2, log2_hashmap=19,
// align_corners=false.
//
// R15 = R12 load structure (quad-fused hash pairs + dense cell records, fused
// prep, evict-first output stores) with 4 levels per thread (4j..4j+3):
//   - inputs loaded once per 4 point-levels
//   - ~20 independent gathers batched per thread
//   - two coalesced float4 stores per thread

#define PRIME1 2654435761u
#define PRIME2 805459861u
#define HASH_MASK 0x7FFFFu
#define TOTAL_PARAMS 7131240
#define NCELLS 299008            // 16^3 + 32^3 + 64^3
#define HSTART 315496            // c_off[3]: start of hash region
#define HCOUNT 6815744           // 13 * 2^19 hash entries
#define HQUADS (HCOUNT / 4)

__device__ __align__(16) __half2 g_embh[TOTAL_PARAMS];   // half2 table (hash region used)
__device__ __align__(32) uint4   g_celld[2 * NCELLS];    // 9.6 MB dense cell table

__constant__ uint32_t c_off[16] = {
    0u, 4920u, 40864u, 315496u,
    839784u, 1364072u, 1888360u, 2412648u,
    2936936u, 3461224u, 3985512u, 4509800u,
    5034088u, 5558376u, 6082664u, 6606952u
};
__constant__ float c_scale[16] = {
    15.f, 31.f, 63.f, 127.f, 255.f, 511.f, 1023.f, 2047.f,
    4095.f, 8191.f, 16383.f, 32767.f, 65535.f, 131071.f, 262143.f, 524287.f
};
__constant__ uint32_t c_celloff[3] = {0u, 4096u, 36864u};

__device__ __forceinline__ uint32_t f2h2(float a, float b)
{
    __half2 h = __floats2half2_rn(a, b);
    return *reinterpret_cast<uint32_t*>(&h);
}

// Fused prep (R12 version, proven): blocks [0, hq_blocks) convert the hash
// region fp32->half2 (4 entries/thread); remaining blocks build dense cell
// records directly from the fp32 source.
__global__ void __launch_bounds__(256)
prep_kernel(const float4* __restrict__ emb4, const float2* __restrict__ emb2,
            int hq_blocks)
{
    if (blockIdx.x < (unsigned)hq_blocks) {
        int i = blockIdx.x * 256 + threadIdx.x;
        if (i < HQUADS) {
            int src = (HSTART / 2) + 2 * i;
            float4 v0 = __ldg(&emb4[src + 0]);
            float4 v1 = __ldg(&emb4[src + 1]);
            uint4 q;
            q.x = f2h2(v0.x, v0.y);
            q.y = f2h2(v0.z, v0.w);
            q.z = f2h2(v1.x, v1.y);
            q.w = f2h2(v1.z, v1.w);
            reinterpret_cast<uint4*>(g_embh + HSTART)[i] = q;
        }
    } else {
        int i = (blockIdx.x - hq_blocks) * 256 + threadIdx.x;
        if (i >= NCELLS) return;

        uint32_t lc, sft, base, off;
        if (i < 4096)        { lc = i;          sft = 4u; base = 17u; off = 0u; }
        else if (i < 36864)  { lc = i - 4096;   sft = 5u; base = 33u; off = 4920u; }
        else                 { lc = i - 36864;  sft = 6u; base = 65u; off = 40864u; }

        uint32_t mask = (1u << sft) - 1u;
        uint32_t gx = lc & mask;
        uint32_t gy = (lc >> sft) & mask;
        uint32_t gz = lc >> (2u * sft);

        uint32_t b2 = base * base;
        uint32_t s = off + gx + gy * base + gz * b2;

        float2 v00a = __ldg(&emb2[s]);
        float2 v00b = __ldg(&emb2[s + 1u]);
        float2 v10a = __ldg(&emb2[s + base]);
        float2 v10b = __ldg(&emb2[s + base + 1u]);
        float2 v01a = __ldg(&emb2[s + b2]);
        float2 v01b = __ldg(&emb2[s + b2 + 1u]);
        float2 v11a = __ldg(&emb2[s + base + b2]);
        float2 v11b = __ldg(&emb2[s + base + b2 + 1u]);

        uint4 qa, qb;
        qa.x = f2h2(v00a.x, v00a.y);  qa.y = f2h2(v00b.x, v00b.y);
        qa.z = f2h2(v10a.x, v10a.y);  qa.w = f2h2(v10b.x, v10b.y);
        qb.x = f2h2(v01a.x, v01a.y);  qb.y = f2h2(v01b.x, v01b.y);
        qb.z = f2h2(v11a.x, v11a.y);  qb.w = f2h2(v11b.x, v11b.y);

        g_celld[2 * i + 0] = qa;
        g_celld[2 * i + 1] = qb;
    }
}

__device__ __forceinline__ uint32_t pick4(uint4 q, uint32_t k)
{
    uint32_t lo = (k & 1u) ? q.y : q.x;
    uint32_t hi = (k & 1u) ? q.w : q.z;
    return (k & 2u) ? hi : lo;
}

__device__ __forceinline__ float2 h2f(uint32_t h)
{
    __half2 v = *reinterpret_cast<__half2*>(&h);
    return __half22float2(v);
}

// Hash-level pair load (optimal: 2-way branch, fused quad or 2 singles)
__device__ __forceinline__ void load_pair(uint32_t iA, uint32_t iB,
                                          float2& ea, float2& eb)
{
    uint32_t diff = iA ^ iB;
    if (diff < 4u) {
        uint4 q = __ldg(reinterpret_cast<const uint4*>(g_embh + (iA & ~3u)));
        ea = h2f(pick4(q, iA & 3u));
        eb = h2f(pick4(q, iB & 3u));
    } else {
        ea = h2f(__ldg(reinterpret_cast<const uint32_t*>(g_embh + iA)));
        eb = h2f(__ldg(reinterpret_cast<const uint32_t*>(g_embh + iB)));
    }
}

// One point-level: gathers + trilinear interp. Returns (ch0, ch1).
__device__ __forceinline__ float2 encode_level(int l, float x, float y, float z)
{
    float scale = c_scale[l];
    float px = fmaf(x, scale, 0.5f);
    float py = fmaf(y, scale, 0.5f);
    float pz = fmaf(z, scale, 0.5f);

    float fx = floorf(px), fy = floorf(py), fz = floorf(pz);
    uint32_t gx = (uint32_t)fx, gy = (uint32_t)fy, gz = (uint32_t)fz;
    float rx = px - fx, ry = py - fy, rz = pz - fz;

    float2 e0, e1, e2c, e3, e4c, e5, e6, e7;

    if (l >= 3) {
        uint32_t off = c_off[l];
        uint32_t x0 = gx,              x1 = gx + 1u;
        uint32_t y0 = gy * PRIME1,     y1 = (gy + 1u) * PRIME1;
        uint32_t z0 = gz * PRIME2,     z1 = (gz + 1u) * PRIME2;
        uint32_t h00 = y0 ^ z0, h10 = y1 ^ z0, h01 = y0 ^ z1, h11 = y1 ^ z1;
        uint32_t i00a = ((x0 ^ h00) & HASH_MASK) + off;
        uint32_t i00b = ((x1 ^ h00) & HASH_MASK) + off;
        uint32_t i10a = ((x0 ^ h10) & HASH_MASK) + off;
        uint32_t i10b = ((x1 ^ h10) & HASH_MASK) + off;
        uint32_t i01a = ((x0 ^ h01) & HASH_MASK) + off;
        uint32_t i01b = ((x1 ^ h01) & HASH_MASK) + off;
        uint32_t i11a = ((x0 ^ h11) & HASH_MASK) + off;
        uint32_t i11b = ((x1 ^ h11) & HASH_MASK) + off;

        load_pair(i00a, i00b, e0,  e1);
        load_pair(i10a, i10b, e2c, e3);
        load_pair(i01a, i01b, e4c, e5);
        load_pair(i11a, i11b, e6,  e7);
    } else {
        uint32_t sft = 4u + (uint32_t)l;
        uint32_t cell = c_celloff[l] + gx + (gy << sft) + (gz << (sft + sft));
        const uint4* cp = &g_celld[2u * cell];
        uint4 qa = __ldg(cp);
        uint4 qb = __ldg(cp + 1);
        e0  = h2f(qa.x);  e1 = h2f(qa.y);
        e2c = h2f(qa.z);  e3 = h2f(qa.w);
        e4c = h2f(qb.x);  e5 = h2f(qb.y);
        e6  = h2f(qb.z);  e7 = h2f(qb.w);
    }

    float wx0 = 1.0f - rx, wx1 = rx;
    float wy0 = 1.0f - ry, wy1 = ry;
    float wz0 = 1.0f - rz, wz1 = rz;

    float w00 = wy0 * wz0, w10 = wy1 * wz0, w01 = wy0 * wz1, w11 = wy1 * wz1;

    float w0 = wx0 * w00, w1 = wx1 * w00;
    float w2 = wx0 * w10, w3 = wx1 * w10;
    float w4 = wx0 * w01, w5 = wx1 * w01;
    float w6 = wx0 * w11, w7 = wx1 * w11;

    float a0 = w0 * e0.x;            float a1 = w0 * e0.y;
    a0 = fmaf(w1, e1.x,  a0);        a1 = fmaf(w1, e1.y,  a1);
    a0 = fmaf(w2, e2c.x, a0);        a1 = fmaf(w2, e2c.y, a1);
    a0 = fmaf(w3, e3.x,  a0);        a1 = fmaf(w3, e3.y,  a1);
    a0 = fmaf(w4, e4c.x, a0);        a1 = fmaf(w4, e4c.y, a1);
    a0 = fmaf(w5, e5.x,  a0);        a1 = fmaf(w5, e5.y,  a1);
    a0 = fmaf(w6, e6.x,  a0);        a1 = fmaf(w6, e6.y,  a1);
    a0 = fmaf(w7, e7.x,  a0);        a1 = fmaf(w7, e7.y,  a1);

    return make_float2(a0, a1);
}

__global__ void __launch_bounds__(256)
grid_encode_kernel(const float* __restrict__ in,
                   float4* __restrict__ out,
                   int B)
{
    int t = blockIdx.x * blockDim.x + threadIdx.x;
    int p = t >> 2;           // point index
    int j = t & 3;            // level quad (4j .. 4j+3)
    if (p >= B) return;

    // map inputs from [-1,1] to [0,1] (once per 4 point-levels)
    float x = (in[p * 3 + 0] + 1.0f) * 0.5f;
    float y = (in[p * 3 + 1] + 1.0f) * 0.5f;
    float z = (in[p * 3 + 2] + 1.0f) * 0.5f;

    float2 r0 = encode_level(4 * j + 0, x, y, z);
    float2 r1 = encode_level(4 * j + 1, x, y, z);
    float2 r2 = encode_level(4 * j + 2, x, y, z);
    float2 r3 = encode_level(4 * j + 3, x, y, z);

    // out[p][8j .. 8j+7]: two coalesced evict-first float4 stores
    __stcs(&out[p * 8 + 2 * j + 0], make_float4(r0.x, r0.y, r1.x, r1.y));
    __stcs(&out[p * 8 + 2 * j + 1], make_float4(r2.x, r2.y, r3.x, r3.y));
}

extern "C" void kernel_launch(void* const* d_in, const int* in_sizes, int n_in,
                              void* d_out, int out_size) {
    const float*  inputs = (const float*)d_in[0];       // [B, 3]
    const float4* emb4   = (const float4*)d_in[1];      // fp32 table as float4
    const float2* emb2   = (const float2*)d_in[1];      // fp32 table as float2
    float4*       out    = (float4*)d_out;              // [B, 8] of float4

    int B = in_sizes[0] / 3;

    // 1) fused prep: hash-region convert + dense cell build
    int hq_blocks   = (HQUADS + 255) / 256;
    int cell_blocks = (NCELLS + 255) / 256;
    prep_kernel<<<hq_blocks + cell_blocks, 256>>>(emb4, emb2, hq_blocks);

    // 2) main encode: 4 threads per point, 4 levels each
    int threads = 256;
    long long total = (long long)B * 4;
    int blocks = (int)((total + threads - 1) / threads);
    grid_encode_kernel<<<blocks, threads>>>(inputs, out, B);
}

// round 17
// speedup vs baseline: 1.1085x; 1.0496x over previous
#include <cuda_runtime.h>
#include <cuda_fp16.h>
#include <cstdint>

// GridEncoder (instant-ngp style), D=3, L=16, C=2, H=16, PLS=2, log2_hashmap=19,
// align_corners=false.
//
// FINAL (== R12, best verified: 250.2us total, main kernel at 100.4% of the
// L1tex line-wavefront roofline):
//   - half2 table (hash region) + dense per-cell 32B records
//   - hash x-pairs: quad-fused LDG.128 when (iA^iB)<4 (75%), else 2x LDG.32
//   - 2 levels per thread, one coalesced evict-first float4 store
//   - single fused prep kernel (hash convert || dense cell build from fp32)

#define PRIME1 2654435761u
#define PRIME2 805459861u
#define HASH_MASK 0x7FFFFu
#define TOTAL_PARAMS 7131240
#define NCELLS 299008            // 16^3 + 32^3 + 64^3
#define HSTART 315496            // c_off[3]: start of hash region
#define HCOUNT 6815744           // 13 * 2^19 hash entries
#define HQUADS (HCOUNT / 4)

__device__ __align__(16) __half2 g_embh[TOTAL_PARAMS];   // half2 table (hash region used)
__device__ __align__(32) uint4   g_celld[2 * NCELLS];    // 9.6 MB dense cell table

__constant__ uint32_t c_off[16] = {
    0u, 4920u, 40864u, 315496u,
    839784u, 1364072u, 1888360u, 2412648u,
    2936936u, 3461224u, 3985512u, 4509800u,
    5034088u, 5558376u, 6082664u, 6606952u
};
__constant__ float c_scale[16] = {
    15.f, 31.f, 63.f, 127.f, 255.f, 511.f, 1023.f, 2047.f,
    4095.f, 8191.f, 16383.f, 32767.f, 65535.f, 131071.f, 262143.f, 524287.f
};
__constant__ uint32_t c_celloff[3] = {0u, 4096u, 36864u};

__device__ __forceinline__ uint32_t f2h2(float a, float b)
{
    __half2 h = __floats2half2_rn(a, b);
    return *reinterpret_cast<uint32_t*>(&h);
}

// Fused prep: blocks [0, hq_blocks) convert the hash region fp32->half2;
// remaining blocks build dense cell records directly from the fp32 source.
__global__ void __launch_bounds__(256)
prep_kernel(const float4* __restrict__ emb4, const float2* __restrict__ emb2,
            int hq_blocks)
{
    if (blockIdx.x < (unsigned)hq_blocks) {
        int i = blockIdx.x * 256 + threadIdx.x;
        if (i < HQUADS) {
            int src = (HSTART / 2) + 2 * i;
            float4 v0 = __ldg(&emb4[src + 0]);
            float4 v1 = __ldg(&emb4[src + 1]);
            uint4 q;
            q.x = f2h2(v0.x, v0.y);
            q.y = f2h2(v0.z, v0.w);
            q.z = f2h2(v1.x, v1.y);
            q.w = f2h2(v1.z, v1.w);
            reinterpret_cast<uint4*>(g_embh + HSTART)[i] = q;
        }
    } else {
        int i = (blockIdx.x - hq_blocks) * 256 + threadIdx.x;
        if (i >= NCELLS) return;

        uint32_t lc, sft, base, off;
        if (i < 4096)        { lc = i;          sft = 4u; base = 17u; off = 0u; }
        else if (i < 36864)  { lc = i - 4096;   sft = 5u; base = 33u; off = 4920u; }
        else                 { lc = i - 36864;  sft = 6u; base = 65u; off = 40864u; }

        uint32_t mask = (1u << sft) - 1u;
        uint32_t gx = lc & mask;
        uint32_t gy = (lc >> sft) & mask;
        uint32_t gz = lc >> (2u * sft);

        uint32_t b2 = base * base;
        uint32_t s = off + gx + gy * base + gz * b2;

        float2 v00a = __ldg(&emb2[s]);
        float2 v00b = __ldg(&emb2[s + 1u]);
        float2 v10a = __ldg(&emb2[s + base]);
        float2 v10b = __ldg(&emb2[s + base + 1u]);
        float2 v01a = __ldg(&emb2[s + b2]);
        float2 v01b = __ldg(&emb2[s + b2 + 1u]);
        float2 v11a = __ldg(&emb2[s + base + b2]);
        float2 v11b = __ldg(&emb2[s + base + b2 + 1u]);

        uint4 qa, qb;
        qa.x = f2h2(v00a.x, v00a.y);  qa.y = f2h2(v00b.x, v00b.y);
        qa.z = f2h2(v10a.x, v10a.y);  qa.w = f2h2(v10b.x, v10b.y);
        qb.x = f2h2(v01a.x, v01a.y);  qb.y = f2h2(v01b.x, v01b.y);
        qb.z = f2h2(v11a.x, v11a.y);  qb.w = f2h2(v11b.x, v11b.y);

        g_celld[2 * i + 0] = qa;
        g_celld[2 * i + 1] = qb;
    }
}

__device__ __forceinline__ uint32_t pick4(uint4 q, uint32_t k)
{
    uint32_t lo = (k & 1u) ? q.y : q.x;
    uint32_t hi = (k & 1u) ? q.w : q.z;
    return (k & 2u) ? hi : lo;
}

__device__ __forceinline__ float2 h2f(uint32_t h)
{
    __half2 v = *reinterpret_cast<__half2*>(&h);
    return __half22float2(v);
}

// Hash-level pair load (optimal structure: 2-way branch, fused quad or 2 singles)
__device__ __forceinline__ void load_pair(uint32_t iA, uint32_t iB,
                                          float2& ea, float2& eb)
{
    uint32_t diff = iA ^ iB;
    if (diff < 4u) {
        uint4 q = __ldg(reinterpret_cast<const uint4*>(g_embh + (iA & ~3u)));
        ea = h2f(pick4(q, iA & 3u));
        eb = h2f(pick4(q, iB & 3u));
    } else {
        ea = h2f(__ldg(reinterpret_cast<const uint32_t*>(g_embh + iA)));
        eb = h2f(__ldg(reinterpret_cast<const uint32_t*>(g_embh + iB)));
    }
}

// One point-level: gathers + trilinear interp. Returns (ch0, ch1).
__device__ __forceinline__ float2 encode_level(int l, float x, float y, float z)
{
    float scale = c_scale[l];
    float px = fmaf(x, scale, 0.5f);
    float py = fmaf(y, scale, 0.5f);
    float pz = fmaf(z, scale, 0.5f);

    float fx = floorf(px), fy = floorf(py), fz = floorf(pz);
    uint32_t gx = (uint32_t)fx, gy = (uint32_t)fy, gz = (uint32_t)fz;
    float rx = px - fx, ry = py - fy, rz = pz - fz;

    float2 e0, e1, e2c, e3, e4c, e5, e6, e7;

    if (l >= 3) {
        uint32_t off = c_off[l];
        uint32_t x0 = gx,              x1 = gx + 1u;
        uint32_t y0 = gy * PRIME1,     y1 = (gy + 1u) * PRIME1;
        uint32_t z0 = gz * PRIME2,     z1 = (gz + 1u) * PRIME2;
        uint32_t h00 = y0 ^ z0, h10 = y1 ^ z0, h01 = y0 ^ z1, h11 = y1 ^ z1;
        uint32_t i00a = ((x0 ^ h00) & HASH_MASK) + off;
        uint32_t i00b = ((x1 ^ h00) & HASH_MASK) + off;
        uint32_t i10a = ((x0 ^ h10) & HASH_MASK) + off;
        uint32_t i10b = ((x1 ^ h10) & HASH_MASK) + off;
        uint32_t i01a = ((x0 ^ h01) & HASH_MASK) + off;
        uint32_t i01b = ((x1 ^ h01) & HASH_MASK) + off;
        uint32_t i11a = ((x0 ^ h11) & HASH_MASK) + off;
        uint32_t i11b = ((x1 ^ h11) & HASH_MASK) + off;

        load_pair(i00a, i00b, e0,  e1);
        load_pair(i10a, i10b, e2c, e3);
        load_pair(i01a, i01b, e4c, e5);
        load_pair(i11a, i11b, e6,  e7);
    } else {
        uint32_t sft = 4u + (uint32_t)l;
        uint32_t cell = c_celloff[l] + gx + (gy << sft) + (gz << (sft + sft));
        const uint4* cp = &g_celld[2u * cell];
        uint4 qa = __ldg(cp);
        uint4 qb = __ldg(cp + 1);
        e0  = h2f(qa.x);  e1 = h2f(qa.y);
        e2c = h2f(qa.z);  e3 = h2f(qa.w);
        e4c = h2f(qb.x);  e5 = h2f(qb.y);
        e6  = h2f(qb.z);  e7 = h2f(qb.w);
    }

    float wx0 = 1.0f - rx, wx1 = rx;
    float wy0 = 1.0f - ry, wy1 = ry;
    float wz0 = 1.0f - rz, wz1 = rz;

    float w00 = wy0 * wz0, w10 = wy1 * wz0, w01 = wy0 * wz1, w11 = wy1 * wz1;

    float w0 = wx0 * w00, w1 = wx1 * w00;
    float w2 = wx0 * w10, w3 = wx1 * w10;
    float w4 = wx0 * w01, w5 = wx1 * w01;
    float w6 = wx0 * w11, w7 = wx1 * w11;

    float a0 = w0 * e0.x;            float a1 = w0 * e0.y;
    a0 = fmaf(w1, e1.x,  a0);        a1 = fmaf(w1, e1.y,  a1);
    a0 = fmaf(w2, e2c.x, a0);        a1 = fmaf(w2, e2c.y, a1);
    a0 = fmaf(w3, e3.x,  a0);        a1 = fmaf(w3, e3.y,  a1);
    a0 = fmaf(w4, e4c.x, a0);        a1 = fmaf(w4, e4c.y, a1);
    a0 = fmaf(w5, e5.x,  a0);        a1 = fmaf(w5, e5.y,  a1);
    a0 = fmaf(w6, e6.x,  a0);        a1 = fmaf(w6, e6.y,  a1);
    a0 = fmaf(w7, e7.x,  a0);        a1 = fmaf(w7, e7.y,  a1);

    return make_float2(a0, a1);
}

__global__ void __launch_bounds__(256)
grid_encode_kernel(const float* __restrict__ in,
                   float4* __restrict__ out,
                   int B)
{
    int t = blockIdx.x * blockDim.x + threadIdx.x;
    int p = t >> 3;           // point index
    int j = t & 7;            // level pair (2j, 2j+1)
    if (p >= B) return;

    // map inputs from [-1,1] to [0,1] (once per 2 point-levels)
    float x = (in[p * 3 + 0] + 1.0f) * 0.5f;
    float y = (in[p * 3 + 1] + 1.0f) * 0.5f;
    float z = (in[p * 3 + 2] + 1.0f) * 0.5f;

    float2 r0 = encode_level(2 * j + 0, x, y, z);
    float2 r1 = encode_level(2 * j + 1, x, y, z);

    // out[p][4j .. 4j+3]: one coalesced evict-first float4 store
    __stcs(&out[p * 8 + j], make_float4(r0.x, r0.y, r1.x, r1.y));
}

extern "C" void kernel_launch(void* const* d_in, const int* in_sizes, int n_in,
                              void* d_out, int out_size) {
    const float*  inputs = (const float*)d_in[0];       // [B, 3]
    const float4* emb4   = (const float4*)d_in[1];      // fp32 table as float4
    const float2* emb2   = (const float2*)d_in[1];      // fp32 table as float2
    float4*       out    = (float4*)d_out;              // [B, 8] of float4

    int B = in_sizes[0] / 3;

    // 1) fused prep: hash-region convert + dense cell build
    int hq_blocks   = (HQUADS + 255) / 256;
    int cell_blocks = (NCELLS + 255) / 256;
    prep_kernel<<<hq_blocks + cell_blocks, 256>>>(emb4, emb2, hq_blocks);

    // 2) main encode: 8 threads per point, 2 levels each
    int threads = 256;
    long long total = (long long)B * 8;
    int blocks = (int)((total + threads - 1) / threads);
    grid_encode_kernel<<<blocks, threads>>>(inputs, out, B);
}